// round 1
// baseline (speedup 1.0000x reference)
#include <cuda_runtime.h>

#define NMAX 16384
#define KNN  11      // neighbors kept (K=12 graph minus self)
#define TPB  128
#define TILE 2048

// Scratch: repacked points (x, y, z, |p|^2). Static device global (no allocs).
__device__ float4 g_pk[NMAX];

__global__ void repack_kernel(const float* __restrict__ p, int n) {
    int i = blockIdx.x * blockDim.x + threadIdx.x;
    if (i < n) {
        float x = p[3 * i + 0];
        float y = p[3 * i + 1];
        float z = p[3 * i + 2];
        g_pk[i] = make_float4(x, y, z, x * x + y * y + z * z);
    }
}

__device__ __forceinline__ void try_insert(
    float d2, float cx, float cy, float cz, int j, int qi,
    float qx, float qy, float qz,
    float w0, float w1, float w2,
    float dist[KNN], float val[KNN])
{
    if (d2 < dist[KNN - 1] && j != qi) {
        float v = fabsf(qx - cx) * w0 + fabsf(qy - cy) * w1 + fabsf(qz - cz) * w2;
        float dd = d2, vv = v;
#pragma unroll
        for (int k = 0; k < KNN; k++) {
            bool lt = dd < dist[k];
            float td = dist[k], tv = val[k];
            if (lt) { dist[k] = dd; val[k] = vv; dd = td; vv = tv; }
        }
    }
}

__global__ __launch_bounds__(TPB) void knn_gcn_kernel(
    const float* __restrict__ W,
    const float* __restrict__ Bb,
    float* __restrict__ out,
    int n)
{
    __shared__ float4 sh[TILE];

    int qi = blockIdx.x * TPB + threadIdx.x;
    int qload = qi < n ? qi : 0;
    float4 q = g_pk[qload];
    float qx = q.x, qy = q.y, qz = q.z, q2 = q.w;

    float w0 = W[0], w1 = W[1], w2 = W[2];
    float bias = Bb[0];

    float dist[KNN], val[KNN];
#pragma unroll
    for (int k = 0; k < KNN; k++) { dist[k] = 3.0e38f; val[k] = 0.0f; }

    for (int base = 0; base < n; base += TILE) {
        // cooperative tile load (coalesced float4)
        for (int t = threadIdx.x; t < TILE; t += TPB) {
            int g = base + t;
            if (g < n) {
                sh[t] = g_pk[g];
            } else {
                sh[t] = make_float4(0.f, 0.f, 0.f, 3.0e38f); // pad: d2 ~ inf
            }
        }
        __syncthreads();

        float worst = dist[KNN - 1];

#pragma unroll 2
        for (int j = 0; j < TILE; j += 4) {
            float4 c0 = sh[j + 0];
            float4 c1 = sh[j + 1];
            float4 c2 = sh[j + 2];
            float4 c3 = sh[j + 3];

            // d2 = q2 + c2 - 2*dot  (same formula as reference)
            float d0 = fmaf(-2.0f, fmaf(qz, c0.z, fmaf(qy, c0.y, qx * c0.x)), q2 + c0.w);
            float d1 = fmaf(-2.0f, fmaf(qz, c1.z, fmaf(qy, c1.y, qx * c1.x)), q2 + c1.w);
            float d2 = fmaf(-2.0f, fmaf(qz, c2.z, fmaf(qy, c2.y, qx * c2.x)), q2 + c2.w);
            float d3 = fmaf(-2.0f, fmaf(qz, c3.z, fmaf(qy, c3.y, qx * c3.x)), q2 + c3.w);

            float m = fminf(fminf(d0, d1), fminf(d2, d3));
            if (m < worst) {
                try_insert(d0, c0.x, c0.y, c0.z, base + j + 0, qi, qx, qy, qz, w0, w1, w2, dist, val);
                try_insert(d1, c1.x, c1.y, c1.z, base + j + 1, qi, qx, qy, qz, w0, w1, w2, dist, val);
                try_insert(d2, c2.x, c2.y, c2.z, base + j + 2, qi, qx, qy, qz, w0, w1, w2, dist, val);
                try_insert(d3, c3.x, c3.y, c3.z, base + j + 3, qi, qx, qy, qz, w0, w1, w2, dist, val);
                worst = dist[KNN - 1];
            }
        }
        __syncthreads();
    }

    if (qi < n) {
        float S = 0.0f;
#pragma unroll
        for (int k = 0; k < KNN; k++) S += val[k];

        float xw0 = qx * w0 + qy * w1 + qz * w2;
        const float inv_s2 = 0.7071067811865475f;
        const float c0f = (1.0f + (float)KNN * inv_s2) / 12.0f; // (1 + 11/sqrt(2)) / 12
        const float c1f = 1.0f / 24.0f;                          // 0.5 * 11 / (12 * 11)
        out[qi] = fmaf(c0f, xw0, fmaf(c1f, S, bias));
    }
}

extern "C" void kernel_launch(void* const* d_in, const int* in_sizes, int n_in,
                              void* d_out, int out_size) {
    const float* p = (const float*)d_in[0];   // [2*8192*3] fp32
    const float* W = (const float*)d_in[1];   // [3]
    const float* b = (const float*)d_in[2];   // [1]
    float* out = (float*)d_out;               // [n,1] fp32

    int n = in_sizes[0] / 3;                  // 16384

    int rblocks = (n + 255) / 256;
    repack_kernel<<<rblocks, 256>>>(p, n);

    int qblocks = (n + TPB - 1) / TPB;
    knn_gcn_kernel<<<qblocks, TPB>>>(W, b, out, n);
}

// round 2
// speedup vs baseline: 1.0963x; 1.0963x over previous
#include <cuda_runtime.h>

#define NMAX 16384
#define KNN  11      // neighbors kept (K=12 graph minus self)
#define TPB  128
#define TILE 2048
#define S    8       // candidate-axis splits

// Static device scratch (no allocations allowed).
__device__ float4 g_pk[NMAX];                 // packed points: x,y,z,|p|^2
__device__ float  g_pd[S * KNN * NMAX];       // partial top-K distances
__device__ int    g_pi[S * KNN * NMAX];       // partial top-K indices

__global__ void repack_kernel(const float* __restrict__ p, int n) {
    int i = blockIdx.x * blockDim.x + threadIdx.x;
    if (i < n) {
        float x = p[3 * i + 0];
        float y = p[3 * i + 1];
        float z = p[3 * i + 2];
        g_pk[i] = make_float4(x, y, z, x * x + y * y + z * z);
    }
}

__device__ __forceinline__ void ins(float d, int j, float dist[KNN], int idxk[KNN]) {
    float dd = d; int jj = j;
#pragma unroll
    for (int k = 0; k < KNN; k++) {
        if (dd < dist[k]) {
            float td = dist[k]; int tj = idxk[k];
            dist[k] = dd; idxk[k] = jj;
            dd = td;      jj = tj;
        }
    }
}

// Phase 1: each block = (128 queries) x (1 candidate split of n/S).
// Keeps per-thread sorted top-11 (dist, idx) over its split.
__global__ __launch_bounds__(TPB) void knn_part_kernel(int n) {
    __shared__ float4 sh[TILE];

    int qi    = blockIdx.x * TPB + threadIdx.x;
    int split = blockIdx.y;
    int chunk = (n + S - 1) / S;
    int cbeg  = split * chunk;
    int cend  = min(cbeg + chunk, n);

    float4 q = g_pk[min(qi, n - 1)];
    float qx = q.x, qy = q.y, qz = q.z, q2 = q.w;

    float dist[KNN]; int idxk[KNN];
#pragma unroll
    for (int k = 0; k < KNN; k++) { dist[k] = 3.0e38f; idxk[k] = -1; }

    for (int base = cbeg; base < cend; base += TILE) {
        // cooperative tile load (coalesced float4)
        for (int t = threadIdx.x; t < TILE; t += TPB) {
            int g = base + t;
            sh[t] = (g < cend) ? g_pk[g] : make_float4(0.f, 0.f, 0.f, 3.0e38f);
        }
        __syncthreads();

        float worst = dist[KNN - 1];

        for (int j = 0; j < TILE; j += 8) {
            float4 c0 = sh[j + 0];
            float4 c1 = sh[j + 1];
            float4 c2 = sh[j + 2];
            float4 c3 = sh[j + 3];
            float4 c4 = sh[j + 4];
            float4 c5 = sh[j + 5];
            float4 c6 = sh[j + 6];
            float4 c7 = sh[j + 7];

            // d2 = q2 + |c|^2 - 2*dot   (matches reference formula)
            float d0 = fmaf(-2.0f, fmaf(qz, c0.z, fmaf(qy, c0.y, qx * c0.x)), q2 + c0.w);
            float d1 = fmaf(-2.0f, fmaf(qz, c1.z, fmaf(qy, c1.y, qx * c1.x)), q2 + c1.w);
            float d2 = fmaf(-2.0f, fmaf(qz, c2.z, fmaf(qy, c2.y, qx * c2.x)), q2 + c2.w);
            float d3 = fmaf(-2.0f, fmaf(qz, c3.z, fmaf(qy, c3.y, qx * c3.x)), q2 + c3.w);
            float d4 = fmaf(-2.0f, fmaf(qz, c4.z, fmaf(qy, c4.y, qx * c4.x)), q2 + c4.w);
            float d5 = fmaf(-2.0f, fmaf(qz, c5.z, fmaf(qy, c5.y, qx * c5.x)), q2 + c5.w);
            float d6 = fmaf(-2.0f, fmaf(qz, c6.z, fmaf(qy, c6.y, qx * c6.x)), q2 + c6.w);
            float d7 = fmaf(-2.0f, fmaf(qz, c7.z, fmaf(qy, c7.y, qx * c7.x)), q2 + c7.w);

            float m = fminf(fminf(fminf(d0, d1), fminf(d2, d3)),
                            fminf(fminf(d4, d5), fminf(d6, d7)));
            if (m < worst) {
                int g = base + j;
                if (d0 < dist[KNN-1] && g + 0 != qi) ins(d0, g + 0, dist, idxk);
                if (d1 < dist[KNN-1] && g + 1 != qi) ins(d1, g + 1, dist, idxk);
                if (d2 < dist[KNN-1] && g + 2 != qi) ins(d2, g + 2, dist, idxk);
                if (d3 < dist[KNN-1] && g + 3 != qi) ins(d3, g + 3, dist, idxk);
                if (d4 < dist[KNN-1] && g + 4 != qi) ins(d4, g + 4, dist, idxk);
                if (d5 < dist[KNN-1] && g + 5 != qi) ins(d5, g + 5, dist, idxk);
                if (d6 < dist[KNN-1] && g + 6 != qi) ins(d6, g + 6, dist, idxk);
                if (d7 < dist[KNN-1] && g + 7 != qi) ins(d7, g + 7, dist, idxk);
                worst = dist[KNN - 1];
            }
        }
        __syncthreads();
    }

    if (qi < n) {
        // Coalesced: query index is fastest dim.
#pragma unroll
        for (int k = 0; k < KNN; k++) {
            g_pd[(split * KNN + k) * NMAX + qi] = dist[k];
            g_pi[(split * KNN + k) * NMAX + qi] = idxk[k];
        }
    }
}

// Phase 2: merge S sorted partial lists (early break), gather winners,
// apply closed-form GCNConv + mean-pool.
__global__ __launch_bounds__(TPB) void merge_kernel(
    const float* __restrict__ W,
    const float* __restrict__ Bb,
    float* __restrict__ out,
    int n)
{
    int qi = blockIdx.x * TPB + threadIdx.x;
    if (qi >= n) return;

    float dist[KNN]; int idxk[KNN];
#pragma unroll
    for (int k = 0; k < KNN; k++) { dist[k] = 3.0e38f; idxk[k] = 0; }

    for (int s = 0; s < S; s++) {
#pragma unroll
        for (int k = 0; k < KNN; k++) {
            float d = g_pd[(s * KNN + k) * NMAX + qi];
            if (d >= dist[KNN - 1]) break;   // lists are sorted ascending
            int j = g_pi[(s * KNN + k) * NMAX + qi];
            ins(d, j, dist, idxk);
        }
    }

    float4 q = g_pk[qi];
    float w0 = W[0], w1 = W[1], w2 = W[2];

    float Ssum = 0.0f;
#pragma unroll
    for (int k = 0; k < KNN; k++) {
        float4 c = g_pk[idxk[k]];
        Ssum += fabsf(q.x - c.x) * w0 + fabsf(q.y - c.y) * w1 + fabsf(q.z - c.z) * w2;
    }

    float xw0 = q.x * w0 + q.y * w1 + q.z * w2;
    const float inv_s2 = 0.7071067811865475f;
    const float c0f = (1.0f + (float)KNN * inv_s2) / 12.0f; // (1 + 11/sqrt(2)) / 12
    const float c1f = 1.0f / 24.0f;                          // 0.5/12
    out[qi] = fmaf(c0f, xw0, fmaf(c1f, Ssum, Bb[0]));
}

extern "C" void kernel_launch(void* const* d_in, const int* in_sizes, int n_in,
                              void* d_out, int out_size) {
    const float* p = (const float*)d_in[0];   // [2*8192*3] fp32
    const float* W = (const float*)d_in[1];   // [3]
    const float* b = (const float*)d_in[2];   // [1]
    float* out = (float*)d_out;               // [n,1] fp32

    int n = in_sizes[0] / 3;                  // 16384

    repack_kernel<<<(n + 255) / 256, 256>>>(p, n);

    dim3 grid((n + TPB - 1) / TPB, S);
    knn_part_kernel<<<grid, TPB>>>(n);

    merge_kernel<<<(n + TPB - 1) / TPB, TPB>>>(W, b, out, n);
}

// round 3
// speedup vs baseline: 2.3574x; 2.1502x over previous
#include <cuda_runtime.h>
#include <math.h>

#define NMAX 16384
#define KNN  11      // neighbors kept (K=12 graph minus self)
#define TPB  128
#define S    8       // candidate-axis splits
#define TILE 2048    // NMAX / S

// Static device scratch (no allocations allowed).
__device__ float4 g_pk[NMAX];             // packed points: x,y,z,|p|^2
__device__ float  g_seed[NMAX];           // shifted seed threshold: seed_d2 - |q|^2
__device__ float  g_pd[S * KNN * NMAX];   // partial top-K shifted distances
__device__ int    g_pi[S * KNN * NMAX];   // partial top-K indices
__device__ int    g_fail_cnt;
__device__ int    g_fail[NMAX];

__global__ void repack_kernel(const float* __restrict__ p, int n) {
    int i = blockIdx.x * blockDim.x + threadIdx.x;
    if (i == 0) g_fail_cnt = 0;
    if (i < n) {
        float x = p[3 * i + 0];
        float y = p[3 * i + 1];
        float z = p[3 * i + 2];
        float q2 = x * x + y * y + z * z;
        g_pk[i] = make_float4(x, y, z, q2);
        // Analytic 11-NN radius estimate from local Gaussian density:
        // lambda = n * (2pi)^{-3/2} * exp(-q2/2);  r^3 = 33/(4pi*lambda)
        float lam = (float)n * 0.063493636f * __expf(-0.5f * q2);
        float f = 2.6260608f / lam;
        float r2 = cbrtf(f * f);                 // expected r11^2
        // Safety factor 2.5x in d^2 (~4x expected count). Shift by -q2 so the
        // hot loop can compare d' = |c|^2 - 2*q.c directly.
        g_seed[i] = 2.5f * r2 - q2;
    }
}

__device__ __forceinline__ void ins(float d, int j, float dist[KNN], int idxk[KNN]) {
    float dd = d; int jj = j;
#pragma unroll
    for (int k = 0; k < KNN; k++) {
        if (dd < dist[k]) {
            float td = dist[k]; int tj = idxk[k];
            dist[k] = dd; idxk[k] = jj;
            dd = td;      jj = tj;
        }
    }
}

// Phase 1: block = (128 queries) x (1 candidate split). Per-thread sorted
// top-11 of shifted distance d' = |c|^2 - 2*q.c, seeded with the analytic
// threshold so inserts are rare.
__global__ __launch_bounds__(TPB) void knn_part_kernel(int n) {
    __shared__ float4 sh[TILE];

    int qi    = blockIdx.x * TPB + threadIdx.x;
    int split = blockIdx.y;
    int cbeg  = split * TILE;
    int cend  = min(cbeg + TILE, n);

    int ql = min(qi, n - 1);
    float4 q = g_pk[ql];
    float qx = q.x, qy = q.y, qz = q.z;
    float seed = g_seed[ql];

    float dist[KNN]; int idxk[KNN];
#pragma unroll
    for (int k = 0; k < KNN; k++) { dist[k] = seed; idxk[k] = -1; }

    for (int t = threadIdx.x; t < TILE; t += TPB) {
        int g = cbeg + t;
        sh[t] = (g < cend) ? g_pk[g] : make_float4(0.f, 0.f, 0.f, 3.0e38f);
    }
    __syncthreads();

    float worst = dist[KNN - 1];

    for (int j = 0; j < TILE; j += 8) {
        float4 c0 = sh[j + 0];
        float4 c1 = sh[j + 1];
        float4 c2 = sh[j + 2];
        float4 c3 = sh[j + 3];
        float4 c4 = sh[j + 4];
        float4 c5 = sh[j + 5];
        float4 c6 = sh[j + 6];
        float4 c7 = sh[j + 7];

        // d' = |c|^2 - 2*(q.c)   (ordering == reference d2 = q2 + |c|^2 - 2 q.c)
        float d0 = fmaf(-2.0f, fmaf(qz, c0.z, fmaf(qy, c0.y, qx * c0.x)), c0.w);
        float d1 = fmaf(-2.0f, fmaf(qz, c1.z, fmaf(qy, c1.y, qx * c1.x)), c1.w);
        float d2 = fmaf(-2.0f, fmaf(qz, c2.z, fmaf(qy, c2.y, qx * c2.x)), c2.w);
        float d3 = fmaf(-2.0f, fmaf(qz, c3.z, fmaf(qy, c3.y, qx * c3.x)), c3.w);
        float d4 = fmaf(-2.0f, fmaf(qz, c4.z, fmaf(qy, c4.y, qx * c4.x)), c4.w);
        float d5 = fmaf(-2.0f, fmaf(qz, c5.z, fmaf(qy, c5.y, qx * c5.x)), c5.w);
        float d6 = fmaf(-2.0f, fmaf(qz, c6.z, fmaf(qy, c6.y, qx * c6.x)), c6.w);
        float d7 = fmaf(-2.0f, fmaf(qz, c7.z, fmaf(qy, c7.y, qx * c7.x)), c7.w);

        float m = fminf(fminf(fminf(d0, d1), fminf(d2, d3)),
                        fminf(fminf(d4, d5), fminf(d6, d7)));
        if (m < worst) {
            int g = cbeg + j;
            if (d0 < worst && g + 0 != qi) ins(d0, g + 0, dist, idxk);
            if (d1 < dist[KNN-1] && g + 1 != qi) ins(d1, g + 1, dist, idxk);
            if (d2 < dist[KNN-1] && g + 2 != qi) ins(d2, g + 2, dist, idxk);
            if (d3 < dist[KNN-1] && g + 3 != qi) ins(d3, g + 3, dist, idxk);
            if (d4 < dist[KNN-1] && g + 4 != qi) ins(d4, g + 4, dist, idxk);
            if (d5 < dist[KNN-1] && g + 5 != qi) ins(d5, g + 5, dist, idxk);
            if (d6 < dist[KNN-1] && g + 6 != qi) ins(d6, g + 6, dist, idxk);
            if (d7 < dist[KNN-1] && g + 7 != qi) ins(d7, g + 7, dist, idxk);
            worst = dist[KNN - 1];
        }
    }

    if (qi < n) {
#pragma unroll
        for (int k = 0; k < KNN; k++) {
            g_pd[(split * KNN + k) * NMAX + qi] = dist[k];
            g_pi[(split * KNN + k) * NMAX + qi] = idxk[k];
        }
    }
}

// Phase 2: merge S sorted partial lists; detect seed failures; apply
// closed-form GCNConv + mean-pool for complete queries.
__global__ __launch_bounds__(TPB) void merge_kernel(
    const float* __restrict__ W,
    const float* __restrict__ Bb,
    float* __restrict__ out,
    int n)
{
    int qi = blockIdx.x * TPB + threadIdx.x;
    if (qi >= n) return;

    float dist[KNN]; int idxk[KNN];
#pragma unroll
    for (int k = 0; k < KNN; k++) { dist[k] = 3.0e38f; idxk[k] = -1; }

    for (int s = 0; s < S; s++) {
#pragma unroll
        for (int k = 0; k < KNN; k++) {
            int o = (s * KNN + k) * NMAX + qi;
            float d = g_pd[o];
            int   j = g_pi[o];
            if (j < 0 || d >= dist[KNN - 1]) break;  // sorted ascending
            ins(d, j, dist, idxk);
        }
    }

    if (idxk[KNN - 1] < 0) {
        // Seed threshold under-covered this query: exact repair later.
        int slot = atomicAdd(&g_fail_cnt, 1);
        g_fail[slot] = qi;
        return;
    }

    float4 q = g_pk[qi];
    float w0 = W[0], w1 = W[1], w2 = W[2];

    float Ssum = 0.0f;
#pragma unroll
    for (int k = 0; k < KNN; k++) {
        float4 c = g_pk[idxk[k]];
        Ssum += fabsf(q.x - c.x) * w0 + fabsf(q.y - c.y) * w1 + fabsf(q.z - c.z) * w2;
    }

    float xw0 = q.x * w0 + q.y * w1 + q.z * w2;
    const float inv_s2 = 0.7071067811865475f;
    const float c0f = (1.0f + (float)KNN * inv_s2) / 12.0f;
    const float c1f = 1.0f / 24.0f;
    out[qi] = fmaf(c0f, xw0, fmaf(c1f, Ssum, Bb[0]));
}

// Phase 3: exact repair for queries the seed missed (expected: none).
// One warp per failed query; lanes scan strided, lane 0 merges.
__global__ __launch_bounds__(32) void repair_kernel(
    const float* __restrict__ W,
    const float* __restrict__ Bb,
    float* __restrict__ out,
    int n)
{
    __shared__ float sd[32 * KNN];
    __shared__ int   si[32 * KNN];

    int lane = threadIdx.x;
    int nf = g_fail_cnt;

    for (int f = blockIdx.x; f < nf; f += gridDim.x) {
        int qi = g_fail[f];
        float4 q = g_pk[qi];
        float qx = q.x, qy = q.y, qz = q.z;

        float dist[KNN]; int idxk[KNN];
#pragma unroll
        for (int k = 0; k < KNN; k++) { dist[k] = 3.0e38f; idxk[k] = -1; }

        for (int j = lane; j < n; j += 32) {
            float4 c = g_pk[j];
            float d = fmaf(-2.0f, fmaf(qz, c.z, fmaf(qy, c.y, qx * c.x)), c.w);
            if (d < dist[KNN - 1] && j != qi) ins(d, j, dist, idxk);
        }
#pragma unroll
        for (int k = 0; k < KNN; k++) {
            sd[lane * KNN + k] = dist[k];
            si[lane * KNN + k] = idxk[k];
        }
        __syncwarp();

        if (lane == 0) {
            int ptr[32];
#pragma unroll
            for (int l = 0; l < 32; l++) ptr[l] = 0;
            float w0 = W[0], w1 = W[1], w2 = W[2];
            float Ssum = 0.0f;
            for (int k = 0; k < KNN; k++) {
                float best = 3.0e38f; int bl = 0;
                for (int l = 0; l < 32; l++) {
                    if (ptr[l] < KNN) {
                        float d = sd[l * KNN + ptr[l]];
                        if (d < best) { best = d; bl = l; }
                    }
                }
                int j = si[bl * KNN + ptr[bl]];
                ptr[bl]++;
                float4 c = g_pk[j];
                Ssum += fabsf(q.x - c.x) * w0 + fabsf(q.y - c.y) * w1
                      + fabsf(q.z - c.z) * w2;
            }
            float xw0 = q.x * w0 + q.y * w1 + q.z * w2;
            const float inv_s2 = 0.7071067811865475f;
            const float c0f = (1.0f + (float)KNN * inv_s2) / 12.0f;
            const float c1f = 1.0f / 24.0f;
            out[qi] = fmaf(c0f, xw0, fmaf(c1f, Ssum, Bb[0]));
        }
        __syncwarp();
    }
}

extern "C" void kernel_launch(void* const* d_in, const int* in_sizes, int n_in,
                              void* d_out, int out_size) {
    const float* p = (const float*)d_in[0];   // [2*8192*3] fp32
    const float* W = (const float*)d_in[1];   // [3]
    const float* b = (const float*)d_in[2];   // [1]
    float* out = (float*)d_out;               // [n,1] fp32

    int n = in_sizes[0] / 3;                  // 16384

    repack_kernel<<<(n + 255) / 256, 256>>>(p, n);

    dim3 grid((n + TPB - 1) / TPB, S);
    knn_part_kernel<<<grid, TPB>>>(n);

    merge_kernel<<<(n + TPB - 1) / TPB, TPB>>>(W, b, out, n);

    repair_kernel<<<128, 32>>>(W, b, out, n);
}